// round 5
// baseline (speedup 1.0000x reference)
#include <cuda_runtime.h>
#include <cuda_bf16.h>
#include <math.h>

// Problem constants
#define B_   8
#define CIN  64
#define COUT 32
#define HIN  128
#define WIN  128
#define HO   256
#define WO   256
#define ATT  16
#define KNUM 2
#define EPS  1e-5f

#define RATIO 0.49803921568627452f   // 127/255

typedef unsigned long long u64;

// Scratch (device globals: no allocation allowed)
__device__ float g_gap[B_ * CIN];               // GAP of (virtually) upsampled x
__device__ float g_weff[B_ * COUT * CIN * 9];   // fully folded per-sample weights
__device__ float g_bias[COUT];                  // folded BN bias

// ---- packed fp32x2 helpers (FFMA2 path) -----------------------------------
__device__ __forceinline__ u64 pack2(float lo, float hi) {
    u64 d;
    asm("mov.b64 %0, {%1, %2};" : "=l"(d) : "f"(lo), "f"(hi));
    return d;
}
__device__ __forceinline__ void fma2(u64& d, u64 a, u64 b) {
    asm("fma.rn.f32x2 %0, %1, %2, %0;" : "+l"(d) : "l"(a), "l"(b));
}
__device__ __forceinline__ float lo2(u64 v) {
    return __uint_as_float((unsigned)v);
}
__device__ __forceinline__ float hi2(u64 v) {
    return __uint_as_float((unsigned)(v >> 32));
}

// ---------------------------------------------------------------------------
// K1: GAP of the bilinear-x2 (align_corners) upsample WITHOUT materializing it.
// mean(up(x)) = (1/65536) * sum_{y,x} R[y]*R[x]*x[y][x]
// ---------------------------------------------------------------------------
__global__ void k_gap(const float* __restrict__ x)
{
    __shared__ float sR[HIN];
    __shared__ float red[256];
    int t = threadIdx.x;

    if (t < HIN) sR[t] = 0.0f;
    __syncthreads();
    if (t < HO) {
        float py = (float)t * RATIO;
        int   y0 = (int)py;
        float wy = py - (float)y0;
        int   y1 = min(y0 + 1, HIN - 1);
        atomicAdd(&sR[y0], 1.0f - wy);
        atomicAdd(&sR[y1], wy);
    }
    __syncthreads();

    int bc = blockIdx.x;
    const float4* __restrict__ plane =
        (const float4*)(x + (size_t)bc * HIN * WIN);

    float lsum = 0.0f;
    for (int idx = t; idx < HIN * WIN / 4; idx += 256) {
        int y  = idx >> 5;            // 32 float4 per 128-wide row
        int c4 = (idx & 31) * 4;
        float4 v = plane[idx];
        float ry = sR[y];
        lsum += ry * (v.x * sR[c4] + v.y * sR[c4 + 1] +
                      v.z * sR[c4 + 2] + v.w * sR[c4 + 3]);
    }
    red[t] = lsum;
    __syncthreads();
    for (int s = 128; s > 0; s >>= 1) {
        if (t < s) red[t] += red[t + s];
        __syncthreads();
    }
    if (t == 0)
        g_gap[bc] = red[0] * (1.0f / (float)(HO * WO));
}

// ---------------------------------------------------------------------------
// K2: attention MLP + full weight folding.
// ---------------------------------------------------------------------------
__global__ void k_attention(
    const float* __restrict__ fc_w,
    const float* __restrict__ bna_g, const float* __restrict__ bna_b,
    const float* __restrict__ bna_m, const float* __restrict__ bna_v,
    const float* __restrict__ ch_w,  const float* __restrict__ ch_b,
    const float* __restrict__ fil_w, const float* __restrict__ fil_b,
    const float* __restrict__ sp_w,  const float* __restrict__ sp_b,
    const float* __restrict__ k_w,   const float* __restrict__ k_b,
    const float* __restrict__ weight,
    const float* __restrict__ bn_g,  const float* __restrict__ bn_b,
    const float* __restrict__ bn_m,  const float* __restrict__ bn_v)
{
    int b = blockIdx.x;
    int t = threadIdx.x;
    __shared__ float sh[ATT];
    __shared__ float sch[CIN];
    __shared__ float sfs[COUT];
    __shared__ float ssp[9];
    __shared__ float sraw[KNUM];
    __shared__ float skk[KNUM];

    if (t < ATT) {
        const float* g = g_gap + b * CIN;
        float acc = 0.0f;
        #pragma unroll
        for (int ci = 0; ci < CIN; ci++) acc += fc_w[t * CIN + ci] * g[ci];
        acc = (acc - bna_m[t]) * rsqrtf(bna_v[t] + EPS) * bna_g[t] + bna_b[t];
        sh[t] = fmaxf(acc, 0.0f);
    }
    __syncthreads();

    if (t < CIN) {
        float a = ch_b[t];
        #pragma unroll
        for (int j = 0; j < ATT; j++) a += ch_w[t * ATT + j] * sh[j];
        sch[t] = 1.0f / (1.0f + expf(-a));
    } else if (t < CIN + COUT) {
        int co = t - CIN;
        float a = fil_b[co];
        #pragma unroll
        for (int j = 0; j < ATT; j++) a += fil_w[co * ATT + j] * sh[j];
        float fil = 1.0f / (1.0f + expf(-a));
        sfs[co] = fil * bn_g[co] * rsqrtf(bn_v[co] + EPS);
    } else if (t < CIN + COUT + 9) {
        int q = t - CIN - COUT;
        float a = sp_b[q];
        #pragma unroll
        for (int j = 0; j < ATT; j++) a += sp_w[q * ATT + j] * sh[j];
        ssp[q] = 1.0f / (1.0f + expf(-a));
    } else if (t < CIN + COUT + 9 + KNUM) {
        int k = t - CIN - COUT - 9;
        float a = k_b[k];
        #pragma unroll
        for (int j = 0; j < ATT; j++) a += k_w[k * ATT + j] * sh[j];
        sraw[k] = a;
    }
    __syncthreads();
    if (t == 0) {
        float m  = fmaxf(sraw[0], sraw[1]);
        float e0 = expf(sraw[0] - m);
        float e1 = expf(sraw[1] - m);
        float inv = 1.0f / (e0 + e1);
        skk[0] = e0 * inv;
        skk[1] = e1 * inv;
    }
    __syncthreads();

    const int WSZ = COUT * CIN * 9;   // 18432
    float* wout = g_weff + b * WSZ;
    for (int idx = t; idx < WSZ; idx += blockDim.x) {
        int co  = idx / (CIN * 9);
        int rem = idx % (CIN * 9);
        int ci  = rem / 9;
        int q   = rem % 9;
        float w = skk[0] * weight[idx] + skk[1] * weight[WSZ + idx];
        wout[idx] = w * ssp[q] * sch[ci] * sfs[co];
    }
    if (b == 0 && t < COUT)
        g_bias[t] = bn_b[t] - bn_m[t] * bn_g[t] * rsqrtf(bn_v[t] + EPS);
}

// ---------------------------------------------------------------------------
// K3: fused bilinear-upsample + direct 3x3 conv + bias + exact GELU,
// mainloop in packed f32x2 (FFMA2).
// __launch_bounds__(256,1): full 255-reg budget -> no spills for the 32 u64
// accumulators + packed row registers (the R3 regression cause).
// ---------------------------------------------------------------------------
#define CI_CHUNK 8
#define TH 8
#define TW 64

__global__ void __launch_bounds__(256, 1) k_conv(const float* __restrict__ x,
                                                 float* __restrict__ out)
{
    __shared__ __align__(16) float sX[CI_CHUNK][TH + 2][TW + 4];  // 10 x 68
    __shared__ u64 sW2[CI_CHUNK][9][COUT];   // (w,w) splat pairs, 18 KB

    int b    = blockIdx.z;
    int row0 = blockIdx.y * TH;
    int col0 = blockIdx.x * TW;
    int tid  = threadIdx.x;
    int tc   = tid >> 6;          // 0..3: cout group (warp-uniform)
    int tp   = tid & 63;
    int rowt = tp >> 3;           // 0..7
    int colt = (tp & 7) * 8;      // 0..56 (8-float aligned -> LDS.64 ok)

    u64 acc2[8][4];
    #pragma unroll
    for (int i = 0; i < 8; i++)
        #pragma unroll
        for (int p = 0; p < 4; p++) acc2[i][p] = 0ull;

    const float* __restrict__ weffb = g_weff + b * (COUT * CIN * 9);

    for (int cc = 0; cc < CIN; cc += CI_CHUNK) {
        // weight chunk -> splat-packed smem: 8*9*32 = 2304 entries
        for (int i = tid; i < CI_CHUNK * COUT * 9; i += 256) {
            int ci  = i / (COUT * 9);
            int rem = i % (COUT * 9);
            int co  = rem / 9;
            int q   = rem % 9;
            float w = weffb[co * (CIN * 9) + (cc + ci) * 9 + q];
            sW2[ci][q][co] = pack2(w, w);
        }
        // input tile + halo (8 x 10 x 66): bilinear upsample on the fly
        for (int i = tid; i < CI_CHUNK * (TH + 2) * (TW + 2); i += 256) {
            int ci  = i / ((TH + 2) * (TW + 2));
            int rem = i % ((TH + 2) * (TW + 2));
            int r   = rem / (TW + 2);
            int c   = rem % (TW + 2);
            int gr  = row0 - 1 + r;
            int gc  = col0 - 1 + c;
            float v = 0.0f;
            if ((unsigned)gr < (unsigned)HO && (unsigned)gc < (unsigned)WO) {
                float py = (float)gr * RATIO;
                int   y0 = (int)py;
                float wy = py - (float)y0;
                int   y1 = min(y0 + 1, HIN - 1);
                float px = (float)gc * RATIO;
                int   x0 = (int)px;
                float wx = px - (float)x0;
                int   x1 = min(x0 + 1, WIN - 1);
                const float* __restrict__ p =
                    x + ((size_t)b * CIN + cc + ci) * (HIN * WIN);
                float a  = __ldg(p + y0 * WIN + x0);
                float bb = __ldg(p + y0 * WIN + x1);
                float cv = __ldg(p + y1 * WIN + x0);
                float d  = __ldg(p + y1 * WIN + x1);
                float v0 = a  * (1.0f - wy) + cv * wy;   // rows first
                float v1 = bb * (1.0f - wy) + d  * wy;
                v = v0 * (1.0f - wx) + v1 * wx;          // then cols
            }
            sX[ci][r][c] = v;
        }
        __syncthreads();

        #pragma unroll 1
        for (int ci = 0; ci < CI_CHUNK; ci++) {
            #pragma unroll
            for (int ky = 0; ky < 3; ky++) {
                // 10-float row as 5 even pairs + 4 repacked odd pairs
                const u64* rp = (const u64*)&sX[ci][rowt + ky][colt];
                u64 E[5];
                #pragma unroll
                for (int j = 0; j < 5; j++) E[j] = rp[j];
                u64 O[4];
                #pragma unroll
                for (int j = 0; j < 4; j++)
                    O[j] = pack2(hi2(E[j]), lo2(E[j + 1]));

                #pragma unroll
                for (int kx = 0; kx < 3; kx++) {
                    int q = ky * 3 + kx;
                    #pragma unroll
                    for (int i = 0; i < 8; i++) {
                        u64 w2 = sW2[ci][q][tc * 8 + i];   // broadcast LDS.64
                        #pragma unroll
                        for (int pp = 0; pp < 4; pp++) {
                            u64 X = (kx == 0) ? E[pp]
                                  : (kx == 1) ? O[pp]
                                              : E[pp + 1];
                            fma2(acc2[i][pp], w2, X);
                        }
                    }
                }
            }
        }
        __syncthreads();
    }

    // epilogue: bias + exact-erf GELU
    #pragma unroll
    for (int i = 0; i < 8; i++) {
        int co = tc * 8 + i;
        float bias = g_bias[co];
        size_t base = (((size_t)b * COUT + co) * HO + (row0 + rowt)) * WO
                      + col0 + colt;
        #pragma unroll
        for (int pp = 0; pp < 4; pp++) {
            float v0 = lo2(acc2[i][pp]) + bias;
            float v1 = hi2(acc2[i][pp]) + bias;
            out[base + 2 * pp]     = 0.5f * v0 * (1.0f + erff(v0 * 0.70710678118654752f));
            out[base + 2 * pp + 1] = 0.5f * v1 * (1.0f + erff(v1 * 0.70710678118654752f));
        }
    }
}

// ---------------------------------------------------------------------------
extern "C" void kernel_launch(void* const* d_in, const int* in_sizes, int n_in,
                              void* d_out, int out_size)
{
    const float* x      = (const float*)d_in[0];
    const float* fc_w   = (const float*)d_in[1];
    const float* bna_g  = (const float*)d_in[2];
    const float* bna_b  = (const float*)d_in[3];
    const float* bna_m  = (const float*)d_in[4];
    const float* bna_v  = (const float*)d_in[5];
    const float* ch_w   = (const float*)d_in[6];
    const float* ch_b   = (const float*)d_in[7];
    const float* fil_w  = (const float*)d_in[8];
    const float* fil_b  = (const float*)d_in[9];
    const float* sp_w   = (const float*)d_in[10];
    const float* sp_b   = (const float*)d_in[11];
    const float* k_w    = (const float*)d_in[12];
    const float* k_b    = (const float*)d_in[13];
    const float* weight = (const float*)d_in[14];
    const float* bn_g   = (const float*)d_in[15];
    const float* bn_b   = (const float*)d_in[16];
    const float* bn_m   = (const float*)d_in[17];
    const float* bn_v   = (const float*)d_in[18];

    k_gap<<<B_ * CIN, 256>>>(x);
    k_attention<<<B_, 256>>>(fc_w, bna_g, bna_b, bna_m, bna_v,
                             ch_w, ch_b, fil_w, fil_b, sp_w, sp_b, k_w, k_b,
                             weight, bn_g, bn_b, bn_m, bn_v);
    k_conv<<<dim3(WO / TW, HO / TH, B_), 256>>>(x, (float*)d_out);
}

// round 7
// speedup vs baseline: 2.6650x; 2.6650x over previous
#include <cuda_runtime.h>
#include <cuda_bf16.h>
#include <math.h>
#include <stdint.h>

#define B_   8
#define CIN  64
#define COUT 32
#define HIN  128
#define WIN  128
#define HO   256
#define WO   256
#define ATT  16
#define KNUM 2
#define EPS  1e-5f
#define RATIO 0.49803921568627452f   // 127/255

typedef unsigned long long u64;
typedef unsigned int u32;

// Scratch device globals
__device__ float g_gap[B_ * CIN];
// folded per-sample weights, bf16 hi/lo split, layout [b][q*2+part][co][ci]
__device__ __nv_bfloat16 g_wsp[B_ * 18 * COUT * CIN];
__device__ float g_bias[COUT];

// ---------------- warp-level MMA helpers (plain sm_103 PTX, sm_80+) --------
__device__ __forceinline__ u32 smem_to_u32(const void* p) {
    u32 a;
    asm("{ .reg .u64 t; cvta.to.shared.u64 t, %1; cvt.u32.u64 %0, t; }"
        : "=r"(a) : "l"(p));
    return a;
}
__device__ __forceinline__ void ldsm_x4(u32* r, u32 addr) {
    asm volatile("ldmatrix.sync.aligned.m8n8.x4.shared.b16 {%0,%1,%2,%3}, [%4];"
                 : "=r"(r[0]), "=r"(r[1]), "=r"(r[2]), "=r"(r[3]) : "r"(addr));
}
__device__ __forceinline__ void ldsm_x2(u32* r, u32 addr) {
    asm volatile("ldmatrix.sync.aligned.m8n8.x2.shared.b16 {%0,%1}, [%2];"
                 : "=r"(r[0]), "=r"(r[1]) : "r"(addr));
}
__device__ __forceinline__ void mma_bf16(float* c, const u32* a, const u32* b) {
    asm volatile(
        "mma.sync.aligned.m16n8k16.row.col.f32.bf16.bf16.f32 "
        "{%0,%1,%2,%3}, {%4,%5,%6,%7}, {%8,%9}, {%0,%1,%2,%3};"
        : "+f"(c[0]), "+f"(c[1]), "+f"(c[2]), "+f"(c[3])
        : "r"(a[0]), "r"(a[1]), "r"(a[2]), "r"(a[3]), "r"(b[0]), "r"(b[1]));
}

// ---------------------------------------------------------------------------
// K1: GAP of virtual bilinear upsample (separable row weights R)
// ---------------------------------------------------------------------------
__global__ void k_gap(const float* __restrict__ x)
{
    __shared__ float sR[HIN];
    __shared__ float red[256];
    int t = threadIdx.x;
    if (t < HIN) sR[t] = 0.0f;
    __syncthreads();
    if (t < HO) {
        float py = (float)t * RATIO;
        int   y0 = (int)py;
        float wy = py - (float)y0;
        int   y1 = min(y0 + 1, HIN - 1);
        atomicAdd(&sR[y0], 1.0f - wy);
        atomicAdd(&sR[y1], wy);
    }
    __syncthreads();
    int bc = blockIdx.x;
    const float* __restrict__ plane = x + (size_t)bc * HIN * WIN;
    float lsum = 0.0f;
    for (int idx = t; idx < HIN * WIN; idx += 256) {
        int y = idx >> 7, c = idx & 127;
        lsum += plane[idx] * sR[y] * sR[c];
    }
    red[t] = lsum;
    __syncthreads();
    for (int s = 128; s > 0; s >>= 1) {
        if (t < s) red[t] += red[t + s];
        __syncthreads();
    }
    if (t == 0) g_gap[bc] = red[0] * (1.0f / (float)(HO * WO));
}

// ---------------------------------------------------------------------------
// K2: attention MLP + weight fold + bf16 hi/lo split into [b][q*2+p][co][ci]
// ---------------------------------------------------------------------------
__global__ void k_attention(
    const float* __restrict__ fc_w,
    const float* __restrict__ bna_g, const float* __restrict__ bna_b,
    const float* __restrict__ bna_m, const float* __restrict__ bna_v,
    const float* __restrict__ ch_w,  const float* __restrict__ ch_b,
    const float* __restrict__ fil_w, const float* __restrict__ fil_b,
    const float* __restrict__ sp_w,  const float* __restrict__ sp_b,
    const float* __restrict__ k_w,   const float* __restrict__ k_b,
    const float* __restrict__ weight,
    const float* __restrict__ bn_g,  const float* __restrict__ bn_b,
    const float* __restrict__ bn_m,  const float* __restrict__ bn_v)
{
    int b = blockIdx.x;
    int t = threadIdx.x;
    __shared__ float sh[ATT];
    __shared__ float sch[CIN];
    __shared__ float sfs[COUT];
    __shared__ float ssp[9];
    __shared__ float sraw[KNUM];
    __shared__ float skk[KNUM];

    if (t < ATT) {
        const float* g = g_gap + b * CIN;
        float acc = 0.0f;
        #pragma unroll
        for (int ci = 0; ci < CIN; ci++) acc += fc_w[t * CIN + ci] * g[ci];
        acc = (acc - bna_m[t]) * rsqrtf(bna_v[t] + EPS) * bna_g[t] + bna_b[t];
        sh[t] = fmaxf(acc, 0.0f);
    }
    __syncthreads();
    if (t < CIN) {
        float a = ch_b[t];
        #pragma unroll
        for (int j = 0; j < ATT; j++) a += ch_w[t * ATT + j] * sh[j];
        sch[t] = 1.0f / (1.0f + expf(-a));
    } else if (t < CIN + COUT) {
        int co = t - CIN;
        float a = fil_b[co];
        #pragma unroll
        for (int j = 0; j < ATT; j++) a += fil_w[co * ATT + j] * sh[j];
        float fil = 1.0f / (1.0f + expf(-a));
        sfs[co] = fil * bn_g[co] * rsqrtf(bn_v[co] + EPS);
    } else if (t < CIN + COUT + 9) {
        int q = t - CIN - COUT;
        float a = sp_b[q];
        #pragma unroll
        for (int j = 0; j < ATT; j++) a += sp_w[q * ATT + j] * sh[j];
        ssp[q] = 1.0f / (1.0f + expf(-a));
    } else if (t < CIN + COUT + 9 + KNUM) {
        int k = t - CIN - COUT - 9;
        float a = k_b[k];
        #pragma unroll
        for (int j = 0; j < ATT; j++) a += k_w[k * ATT + j] * sh[j];
        sraw[k] = a;
    }
    __syncthreads();
    if (t == 0) {
        float m  = fmaxf(sraw[0], sraw[1]);
        float e0 = expf(sraw[0] - m);
        float e1 = expf(sraw[1] - m);
        float inv = 1.0f / (e0 + e1);
        skk[0] = e0 * inv;
        skk[1] = e1 * inv;
    }
    __syncthreads();

    const int WSZ = COUT * CIN * 9;
    for (int idx = t; idx < WSZ; idx += blockDim.x) {
        int co  = idx / (CIN * 9);
        int rem = idx % (CIN * 9);
        int ci  = rem / 9;
        int q   = rem % 9;
        float w = skk[0] * weight[idx] + skk[1] * weight[WSZ + idx];
        w = w * ssp[q] * sch[ci] * sfs[co];
        __nv_bfloat16 wh = __float2bfloat16(w);
        __nv_bfloat16 wl = __float2bfloat16(w - __bfloat162float(wh));
        size_t base = ((size_t)b * 18 + q * 2) * COUT * CIN + (size_t)co * CIN + ci;
        g_wsp[base] = wh;                      // part 0 (hi)
        g_wsp[base + (size_t)COUT * CIN] = wl; // part 1 (lo)
    }
    if (b == 0 && t < COUT)
        g_bias[t] = bn_b[t] - bn_m[t] * bn_g[t] * rsqrtf(bn_v[t] + EPS);
}

// ---------------------------------------------------------------------------
// K3: implicit-GEMM conv on HMMA (mma.sync m16n8k16 bf16, hi/lo 3-pass).
// CTA tile: (b, 4 output rows x 64 cols) = 512 px. 8 warps; warp = 32 px x
// 32 cout. A smem: 6 input rows x 66 px x 64 cin, hi+lo bf16, upsample
// computed on the fly. B smem: 18 (hi/lo x 9 taps) 32x64 bf16 matrices.
// ---------------------------------------------------------------------------
#define AROWB 8448            // 66 * 128 bytes
#define APART 50688           // 6 * AROWB
#define OFF_B 0               // 18 * 4096 = 73728
#define OFF_A 73728
#define SMEM_TOTAL (OFF_A + 2 * APART)   // 175104

#define SWZC(byte, r) ((byte) ^ (((r) & 7) << 4))

__global__ void __launch_bounds__(256, 1)
k_conv(const float* __restrict__ x, float* __restrict__ out)
{
    extern __shared__ char smem[];
    u32 sb = smem_to_u32(smem);
    int tid  = threadIdx.x;
    int w    = tid >> 5;
    int lane = tid & 31;
    int b    = blockIdx.z;
    int r0   = blockIdx.y * 4;
    int c0   = blockIdx.x * 64;

    // ---- fill B: 2 parts x 9 q x 32 n x 8 chunks ---------------------------
    for (int i = tid; i < 4608; i += 256) {
        int part = i / 2304;
        int rem  = i % 2304;
        int q    = rem / 256;
        int rem2 = rem % 256;
        int n    = rem2 >> 3;
        int g    = rem2 & 7;
        uint4 v = *(const uint4*)(g_wsp +
            (((size_t)b * 18 + q * 2 + part) * COUT + n) * CIN + g * 8);
        *(uint4*)(smem + OFF_B + (q * 2 + part) * 4096 + n * 128 +
                  SWZC(g * 16, n)) = v;
    }

    // ---- fill A: 6 rows x 8 ci-chunks x 66 px (p fastest: coalesced) ------
    for (int i = tid; i < 6 * 8 * 66; i += 256) {
        int row = i / (8 * 66);
        int rem = i % (8 * 66);
        int g   = rem / 66;
        int p   = rem % 66;
        int oy  = r0 - 1 + row;
        int oc  = c0 - 1 + p;
        u32 hw[4] = {0, 0, 0, 0}, lw[4] = {0, 0, 0, 0};
        if ((unsigned)oy < (unsigned)HO && (unsigned)oc < (unsigned)WO) {
            float py = (float)oy * RATIO;
            int   y0 = (int)py;
            float wy = py - (float)y0;
            int   y1 = min(y0 + 1, HIN - 1);
            float px = (float)oc * RATIO;
            int   x0 = (int)px;
            float wx = px - (float)x0;
            int   x1 = min(x0 + 1, WIN - 1);
            #pragma unroll
            for (int k = 0; k < 8; k++) {
                const float* pl = x + ((size_t)b * CIN + g * 8 + k) * (HIN * WIN);
                float a  = __ldg(pl + y0 * WIN + x0);
                float bb = __ldg(pl + y0 * WIN + x1);
                float cv = __ldg(pl + y1 * WIN + x0);
                float d  = __ldg(pl + y1 * WIN + x1);
                float v0 = a  * (1.0f - wy) + cv * wy;   // rows first
                float v1 = bb * (1.0f - wy) + d  * wy;
                float v  = v0 * (1.0f - wx) + v1 * wx;   // then cols
                __nv_bfloat16 vh = __float2bfloat16(v);
                __nv_bfloat16 vl = __float2bfloat16(v - __bfloat162float(vh));
                hw[k >> 1] |= (u32)__bfloat16_as_ushort(vh) << ((k & 1) * 16);
                lw[k >> 1] |= (u32)__bfloat16_as_ushort(vl) << ((k & 1) * 16);
            }
        }
        u32 off = (u32)(row * AROWB + p * 128 + SWZC(g * 16, p));
        *(uint4*)(smem + OFF_A + off)         = make_uint4(hw[0], hw[1], hw[2], hw[3]);
        *(uint4*)(smem + OFF_A + APART + off) = make_uint4(lw[0], lw[1], lw[2], lw[3]);
    }
    __syncthreads();

    // ---- mainloop: 3 passes x 9 taps x 4 k-steps --------------------------
    float acc[2][4][4];
    #pragma unroll
    for (int mt = 0; mt < 2; mt++)
        #pragma unroll
        for (int nt = 0; nt < 4; nt++)
            #pragma unroll
            for (int r = 0; r < 4; r++) acc[mt][nt][r] = 0.0f;

    int mrow = w >> 1;             // output row within tile (0..3)
    int mcol = (w & 1) * 32;       // col base within 64-tile

    #pragma unroll 1
    for (int pass = 0; pass < 3; pass++) {
        int ap = (pass == 2) ? 1 : 0;   // A part (hi,hi,lo)
        int bp = (pass == 1) ? 1 : 0;   // B part (hi,lo,hi)
        #pragma unroll 1
        for (int q = 0; q < 9; q++) {
            int ky = q / 3, kx = q % 3;
            u32 arow  = sb + OFF_A + ap * APART + (mrow + ky) * AROWB;
            u32 bbase = sb + OFF_B + (q * 2 + bp) * 4096;
            #pragma unroll
            for (int ks = 0; ks < 4; ks++) {
                int kb = ks * 32;                 // 16 bf16 = 32 bytes
                u32 bfr[4][2];
                #pragma unroll
                for (int nt = 0; nt < 4; nt++) {
                    int n = nt * 8 + (lane & 7);
                    u32 addr = bbase + n * 128 +
                               SWZC(kb + ((lane >> 3) & 1) * 16, n);
                    ldsm_x2(bfr[nt], addr);
                }
                #pragma unroll
                for (int mt = 0; mt < 2; mt++) {
                    int p = mcol + mt * 16 + (lane & 15) + kx;
                    u32 addr = arow + p * 128 +
                               SWZC(kb + ((lane >> 4) ? 16 : 0), p);
                    u32 afr[4];
                    ldsm_x4(afr, addr);
                    #pragma unroll
                    for (int nt = 0; nt < 4; nt++)
                        mma_bf16(acc[mt][nt], afr, bfr[nt]);
                }
            }
        }
    }

    // ---- epilogue: bias + exact-erf GELU ----------------------------------
    int row = r0 + mrow;
    #pragma unroll
    for (int mt = 0; mt < 2; mt++) {
        int col = c0 + mcol + mt * 16 + (lane >> 2);
        #pragma unroll
        for (int nt = 0; nt < 4; nt++) {
            int co0 = nt * 8 + (lane & 3) * 2;
            float b0 = g_bias[co0];
            float b1 = g_bias[co0 + 1];
            #pragma unroll
            for (int r = 0; r < 4; r++) {
                int co = co0 + (r & 1);
                int cc = col + ((r >> 1) ? 8 : 0);
                float v = acc[mt][nt][r] + ((r & 1) ? b1 : b0);
                out[(((size_t)b * COUT + co) * HO + row) * WO + cc] =
                    0.5f * v * (1.0f + erff(v * 0.70710678118654752f));
            }
        }
    }
}

// ---------------------------------------------------------------------------
extern "C" void kernel_launch(void* const* d_in, const int* in_sizes, int n_in,
                              void* d_out, int out_size)
{
    const float* x      = (const float*)d_in[0];
    const float* fc_w   = (const float*)d_in[1];
    const float* bna_g  = (const float*)d_in[2];
    const float* bna_b  = (const float*)d_in[3];
    const float* bna_m  = (const float*)d_in[4];
    const float* bna_v  = (const float*)d_in[5];
    const float* ch_w   = (const float*)d_in[6];
    const float* ch_b   = (const float*)d_in[7];
    const float* fil_w  = (const float*)d_in[8];
    const float* fil_b  = (const float*)d_in[9];
    const float* sp_w   = (const float*)d_in[10];
    const float* sp_b   = (const float*)d_in[11];
    const float* k_w    = (const float*)d_in[12];
    const float* k_b    = (const float*)d_in[13];
    const float* weight = (const float*)d_in[14];
    const float* bn_g   = (const float*)d_in[15];
    const float* bn_b   = (const float*)d_in[16];
    const float* bn_m   = (const float*)d_in[17];
    const float* bn_v   = (const float*)d_in[18];

    cudaFuncSetAttribute(k_conv, cudaFuncAttributeMaxDynamicSharedMemorySize,
                         SMEM_TOTAL);

    k_gap<<<B_ * CIN, 256>>>(x);
    k_attention<<<B_, 256>>>(fc_w, bna_g, bna_b, bna_m, bna_v,
                             ch_w, ch_b, fil_w, fil_b, sp_w, sp_b, k_w, k_b,
                             weight, bn_g, bn_b, bn_m, bn_v);
    k_conv<<<dim3(WO / 64, HO / 4, B_), 256, SMEM_TOTAL>>>(x, (float*)d_out);
}

// round 9
// speedup vs baseline: 3.5452x; 1.3303x over previous
#include <cuda_runtime.h>
#include <cuda_fp16.h>
#include <math.h>
#include <stdint.h>

#define B_   8
#define CIN  64
#define COUT 32
#define HIN  128
#define WIN  128
#define HO   256
#define WO   256
#define ATT  16
#define KNUM 2
#define EPS  1e-5f
#define RATIO 0.49803921568627452f   // 127/255

typedef unsigned long long u64;
typedef unsigned int u32;

// Scratch device globals
__device__ float g_gap[B_ * CIN];
// folded per-sample weights, fp16 (hi only; B residual ~2^-12 is the accepted
// error term), layout [b][q][co][ci]
__device__ __half g_w[B_ * 9 * COUT * CIN];
__device__ float g_bias[COUT];

// ---------------- warp-level MMA helpers (plain sm_103 PTX, sm_80+) --------
__device__ __forceinline__ u32 smem_to_u32(const void* p) {
    u32 a;
    asm("{ .reg .u64 t; cvta.to.shared.u64 t, %1; cvt.u32.u64 %0, t; }"
        : "=r"(a) : "l"(p));
    return a;
}
__device__ __forceinline__ void ldsm_x4(u32* r, u32 addr) {
    asm volatile("ldmatrix.sync.aligned.m8n8.x4.shared.b16 {%0,%1,%2,%3}, [%4];"
                 : "=r"(r[0]), "=r"(r[1]), "=r"(r[2]), "=r"(r[3]) : "r"(addr));
}
__device__ __forceinline__ void ldsm_x2(u32* r, u32 addr) {
    asm volatile("ldmatrix.sync.aligned.m8n8.x2.shared.b16 {%0,%1}, [%2];"
                 : "=r"(r[0]), "=r"(r[1]) : "r"(addr));
}
__device__ __forceinline__ void mma_fp16(float* c, const u32* a, const u32* b) {
    asm volatile(
        "mma.sync.aligned.m16n8k16.row.col.f32.f16.f16.f32 "
        "{%0,%1,%2,%3}, {%4,%5,%6,%7}, {%8,%9}, {%0,%1,%2,%3};"
        : "+f"(c[0]), "+f"(c[1]), "+f"(c[2]), "+f"(c[3])
        : "r"(a[0]), "r"(a[1]), "r"(a[2]), "r"(a[3]), "r"(b[0]), "r"(b[1]));
}

// ---------------------------------------------------------------------------
// K1: GAP of virtual bilinear upsample (separable row weights R)
// ---------------------------------------------------------------------------
__global__ void k_gap(const float* __restrict__ x)
{
    __shared__ float sR[HIN];
    __shared__ float red[256];
    int t = threadIdx.x;
    if (t < HIN) sR[t] = 0.0f;
    __syncthreads();
    if (t < HO) {
        float py = (float)t * RATIO;
        int   y0 = (int)py;
        float wy = py - (float)y0;
        int   y1 = min(y0 + 1, HIN - 1);
        atomicAdd(&sR[y0], 1.0f - wy);
        atomicAdd(&sR[y1], wy);
    }
    __syncthreads();
    int bc = blockIdx.x;
    const float* __restrict__ plane = x + (size_t)bc * HIN * WIN;
    float lsum = 0.0f;
    for (int idx = t; idx < HIN * WIN; idx += 256) {
        int y = idx >> 7, c = idx & 127;
        lsum += plane[idx] * sR[y] * sR[c];
    }
    red[t] = lsum;
    __syncthreads();
    for (int s = 128; s > 0; s >>= 1) {
        if (t < s) red[t] += red[t + s];
        __syncthreads();
    }
    if (t == 0) g_gap[bc] = red[0] * (1.0f / (float)(HO * WO));
}

// ---------------------------------------------------------------------------
// K2: attention MLP + weight fold -> fp16 weights [b][q][co][ci]
// ---------------------------------------------------------------------------
__global__ void k_attention(
    const float* __restrict__ fc_w,
    const float* __restrict__ bna_g, const float* __restrict__ bna_b,
    const float* __restrict__ bna_m, const float* __restrict__ bna_v,
    const float* __restrict__ ch_w,  const float* __restrict__ ch_b,
    const float* __restrict__ fil_w, const float* __restrict__ fil_b,
    const float* __restrict__ sp_w,  const float* __restrict__ sp_b,
    const float* __restrict__ k_w,   const float* __restrict__ k_b,
    const float* __restrict__ weight,
    const float* __restrict__ bn_g,  const float* __restrict__ bn_b,
    const float* __restrict__ bn_m,  const float* __restrict__ bn_v)
{
    int b = blockIdx.x;
    int t = threadIdx.x;
    __shared__ float sh[ATT];
    __shared__ float sch[CIN];
    __shared__ float sfs[COUT];
    __shared__ float ssp[9];
    __shared__ float sraw[KNUM];
    __shared__ float skk[KNUM];

    if (t < ATT) {
        const float* g = g_gap + b * CIN;
        float acc = 0.0f;
        #pragma unroll
        for (int ci = 0; ci < CIN; ci++) acc += fc_w[t * CIN + ci] * g[ci];
        acc = (acc - bna_m[t]) * rsqrtf(bna_v[t] + EPS) * bna_g[t] + bna_b[t];
        sh[t] = fmaxf(acc, 0.0f);
    }
    __syncthreads();
    if (t < CIN) {
        float a = ch_b[t];
        #pragma unroll
        for (int j = 0; j < ATT; j++) a += ch_w[t * ATT + j] * sh[j];
        sch[t] = 1.0f / (1.0f + expf(-a));
    } else if (t < CIN + COUT) {
        int co = t - CIN;
        float a = fil_b[co];
        #pragma unroll
        for (int j = 0; j < ATT; j++) a += fil_w[co * ATT + j] * sh[j];
        float fil = 1.0f / (1.0f + expf(-a));
        sfs[co] = fil * bn_g[co] * rsqrtf(bn_v[co] + EPS);
    } else if (t < CIN + COUT + 9) {
        int q = t - CIN - COUT;
        float a = sp_b[q];
        #pragma unroll
        for (int j = 0; j < ATT; j++) a += sp_w[q * ATT + j] * sh[j];
        ssp[q] = 1.0f / (1.0f + expf(-a));
    } else if (t < CIN + COUT + 9 + KNUM) {
        int k = t - CIN - COUT - 9;
        float a = k_b[k];
        #pragma unroll
        for (int j = 0; j < ATT; j++) a += k_w[k * ATT + j] * sh[j];
        sraw[k] = a;
    }
    __syncthreads();
    if (t == 0) {
        float m  = fmaxf(sraw[0], sraw[1]);
        float e0 = expf(sraw[0] - m);
        float e1 = expf(sraw[1] - m);
        float inv = 1.0f / (e0 + e1);
        skk[0] = e0 * inv;
        skk[1] = e1 * inv;
    }
    __syncthreads();

    const int WSZ = COUT * CIN * 9;
    for (int idx = t; idx < WSZ; idx += blockDim.x) {
        int co  = idx / (CIN * 9);
        int rem = idx % (CIN * 9);
        int ci  = rem / 9;
        int q   = rem % 9;
        float w = skk[0] * weight[idx] + skk[1] * weight[WSZ + idx];
        w = w * ssp[q] * sch[ci] * sfs[co];
        g_w[(((size_t)b * 9 + q) * COUT + co) * CIN + ci] = __float2half(w);
    }
    if (b == 0 && t < COUT)
        g_bias[t] = bn_b[t] - bn_m[t] * bn_g[t] * rsqrtf(bn_v[t] + EPS);
}

// ---------------------------------------------------------------------------
// K3: implicit-GEMM conv on HMMA (mma.sync m16n8k16 fp16, hi/lo 2-pass).
// CTA tile: (b, 2 output rows x 64 cols). 8 warps; warp = 16 px x 32 cout.
// A smem: 2 parts x 4 input rows x 66 px x 64 cin fp16 (upsample on the fly).
// B smem: 9 tap matrices 32x64 fp16 (hi only). 104.4 KB -> 2 CTAs/SM.
// ---------------------------------------------------------------------------
#define AROWB 8448            // 66 * 128 bytes
#define APART 33792           // 4 * AROWB
#define OFF_B 0               // 9 * 4096 = 36864
#define OFF_A 36864
#define SMEM_TOTAL (OFF_A + 2 * APART)   // 104448

#define SWZC(byte, r) ((byte) ^ (((r) & 7) << 4))

__global__ void __launch_bounds__(256, 2)
k_conv(const float* __restrict__ x, float* __restrict__ out)
{
    extern __shared__ char smem[];
    u32 sb = smem_to_u32(smem);
    int tid  = threadIdx.x;
    int w    = tid >> 5;
    int lane = tid & 31;
    int b    = blockIdx.z;
    int r0   = blockIdx.y * 2;
    int c0   = blockIdx.x * 64;

    // ---- fill B: 9 q x 32 n x 8 chunks ------------------------------------
    for (int i = tid; i < 2304; i += 256) {
        int q    = i / 256;
        int rem2 = i % 256;
        int n    = rem2 >> 3;
        int g    = rem2 & 7;
        uint4 v = *(const uint4*)(g_w +
            (((size_t)b * 9 + q) * COUT + n) * CIN + g * 8);
        *(uint4*)(smem + OFF_B + q * 4096 + n * 128 + SWZC(g * 16, n)) = v;
    }

    // ---- fill A: 4 rows x 8 ci-chunks x 66 px, fp16 hi/lo ------------------
    for (int i = tid; i < 4 * 8 * 66; i += 256) {
        int row = i / (8 * 66);
        int rem = i % (8 * 66);
        int g   = rem / 66;
        int p   = rem % 66;
        int oy  = r0 - 1 + row;
        int oc  = c0 - 1 + p;
        u32 hw[4] = {0, 0, 0, 0}, lw[4] = {0, 0, 0, 0};
        if ((unsigned)oy < (unsigned)HO && (unsigned)oc < (unsigned)WO) {
            float py = (float)oy * RATIO;
            int   y0 = (int)py;
            float wy = py - (float)y0;
            int   y1 = min(y0 + 1, HIN - 1);
            float px = (float)oc * RATIO;
            int   x0 = (int)px;
            float wx = px - (float)x0;
            int   x1 = min(x0 + 1, WIN - 1);
            #pragma unroll
            for (int k = 0; k < 8; k++) {
                const float* pl = x + ((size_t)b * CIN + g * 8 + k) * (HIN * WIN);
                float a  = __ldg(pl + y0 * WIN + x0);
                float bb = __ldg(pl + y0 * WIN + x1);
                float cv = __ldg(pl + y1 * WIN + x0);
                float d  = __ldg(pl + y1 * WIN + x1);
                float v0 = a  * (1.0f - wy) + cv * wy;   // rows first
                float v1 = bb * (1.0f - wy) + d  * wy;
                float v  = v0 * (1.0f - wx) + v1 * wx;   // then cols
                __half vh = __float2half(v);
                __half vl = __float2half(v - __half2float(vh));
                hw[k >> 1] |= (u32)__half_as_ushort(vh) << ((k & 1) * 16);
                lw[k >> 1] |= (u32)__half_as_ushort(vl) << ((k & 1) * 16);
            }
        }
        u32 off = (u32)(row * AROWB + p * 128 + SWZC(g * 16, p));
        *(uint4*)(smem + OFF_A + off)         = make_uint4(hw[0], hw[1], hw[2], hw[3]);
        *(uint4*)(smem + OFF_A + APART + off) = make_uint4(lw[0], lw[1], lw[2], lw[3]);
    }
    __syncthreads();

    // ---- mainloop: 2 passes (Ah*Bh, Al*Bh) x 9 taps x 4 k-steps -----------
    float acc[4][4];
    #pragma unroll
    for (int nt = 0; nt < 4; nt++)
        #pragma unroll
        for (int r = 0; r < 4; r++) acc[nt][r] = 0.0f;

    int wrow = w >> 2;             // output row within tile (0..1)
    int wcol = (w & 3) * 16;       // col base within 64-tile

    #pragma unroll 1
    for (int pass = 0; pass < 2; pass++) {
        #pragma unroll 1
        for (int q = 0; q < 9; q++) {
            int ky = q / 3, kx = q % 3;
            u32 arow  = sb + OFF_A + pass * APART + (wrow + ky) * AROWB;
            u32 bbase = sb + OFF_B + q * 4096;
            #pragma unroll
            for (int ks = 0; ks < 4; ks++) {
                int kb = ks * 32;                 // 16 fp16 = 32 bytes
                u32 afr[4];
                {
                    int p = wcol + (lane & 15) + kx;
                    u32 addr = arow + p * 128 +
                               SWZC(kb + ((lane >> 4) ? 16 : 0), p);
                    ldsm_x4(afr, addr);
                }
                #pragma unroll
                for (int nt = 0; nt < 4; nt++) {
                    int n = nt * 8 + (lane & 7);
                    u32 addr = bbase + n * 128 +
                               SWZC(kb + ((lane >> 3) & 1) * 16, n);
                    u32 bfr[2];
                    ldsm_x2(bfr, addr);
                    mma_fp16(acc[nt], afr, bfr);
                }
            }
        }
    }

    // ---- epilogue: bias + exact-erf GELU ----------------------------------
    int row  = r0 + wrow;
    int colb = c0 + wcol + (lane >> 2);
    #pragma unroll
    for (int nt = 0; nt < 4; nt++) {
        int co0 = nt * 8 + (lane & 3) * 2;
        float b0 = g_bias[co0];
        float b1 = g_bias[co0 + 1];
        #pragma unroll
        for (int r = 0; r < 4; r++) {
            int co = co0 + (r & 1);
            int cc = colb + ((r >> 1) ? 8 : 0);
            float v = acc[nt][r] + ((r & 1) ? b1 : b0);
            out[(((size_t)b * COUT + co) * HO + row) * WO + cc] =
                0.5f * v * (1.0f + erff(v * 0.70710678118654752f));
        }
    }
}

// ---------------------------------------------------------------------------
extern "C" void kernel_launch(void* const* d_in, const int* in_sizes, int n_in,
                              void* d_out, int out_size)
{
    const float* x      = (const float*)d_in[0];
    const float* fc_w   = (const float*)d_in[1];
    const float* bna_g  = (const float*)d_in[2];
    const float* bna_b  = (const float*)d_in[3];
    const float* bna_m  = (const float*)d_in[4];
    const float* bna_v  = (const float*)d_in[5];
    const float* ch_w   = (const float*)d_in[6];
    const float* ch_b   = (const float*)d_in[7];
    const float* fil_w  = (const float*)d_in[8];
    const float* fil_b  = (const float*)d_in[9];
    const float* sp_w   = (const float*)d_in[10];
    const float* sp_b   = (const float*)d_in[11];
    const float* k_w    = (const float*)d_in[12];
    const float* k_b    = (const float*)d_in[13];
    const float* weight = (const float*)d_in[14];
    const float* bn_g   = (const float*)d_in[15];
    const float* bn_b   = (const float*)d_in[16];
    const float* bn_m   = (const float*)d_in[17];
    const float* bn_v   = (const float*)d_in[18];

    cudaFuncSetAttribute(k_conv, cudaFuncAttributeMaxDynamicSharedMemorySize,
                         SMEM_TOTAL);

    k_gap<<<B_ * CIN, 256>>>(x);
    k_attention<<<B_, 256>>>(fc_w, bna_g, bna_b, bna_m, bna_v,
                             ch_w, ch_b, fil_w, fil_b, sp_w, sp_b, k_w, k_b,
                             weight, bn_g, bn_b, bn_m, bn_v);
    k_conv<<<dim3(WO / 64, HO / 2, B_), 256, SMEM_TOTAL>>>(x, (float*)d_out);
}

// round 10
// speedup vs baseline: 4.0380x; 1.1390x over previous
#include <cuda_runtime.h>
#include <cuda_fp16.h>
#include <math.h>
#include <stdint.h>

#define B_   8
#define CIN  64
#define COUT 32
#define HIN  128
#define WIN  128
#define HO   256
#define WO   256
#define ATT  16
#define KNUM 2
#define EPS  1e-5f
#define RATIO 0.49803921568627452f   // 127/255

typedef unsigned long long u64;
typedef unsigned int u32;

// Scratch device globals
__device__ float g_gap[B_ * CIN];                 // mean of upsampled x
// upsampled image, fp16, layout [b][g=ci/8][oy][ox][8ci] (uint4 per px-chunk)
__device__ __half g_xh[(size_t)B_ * CIN * HO * WO];
// folded per-sample weights, fp16, layout [b][q][co][ci]
__device__ __half g_w[B_ * 9 * COUT * CIN];
__device__ float g_bias[COUT];

// ---------------- warp-level MMA helpers (plain sm_103 PTX, sm_80+) --------
__device__ __forceinline__ u32 smem_to_u32(const void* p) {
    u32 a;
    asm("{ .reg .u64 t; cvta.to.shared.u64 t, %1; cvt.u32.u64 %0, t; }"
        : "=r"(a) : "l"(p));
    return a;
}
__device__ __forceinline__ void ldsm_x4(u32* r, u32 addr) {
    asm volatile("ldmatrix.sync.aligned.m8n8.x4.shared.b16 {%0,%1,%2,%3}, [%4];"
                 : "=r"(r[0]), "=r"(r[1]), "=r"(r[2]), "=r"(r[3]) : "r"(addr));
}
__device__ __forceinline__ void ldsm_x2(u32* r, u32 addr) {
    asm volatile("ldmatrix.sync.aligned.m8n8.x2.shared.b16 {%0,%1}, [%2];"
                 : "=r"(r[0]), "=r"(r[1]) : "r"(addr));
}
__device__ __forceinline__ void mma_fp16(float* c, const u32* a, const u32* b) {
    asm volatile(
        "mma.sync.aligned.m16n8k16.row.col.f32.f16.f16.f32 "
        "{%0,%1,%2,%3}, {%4,%5,%6,%7}, {%8,%9}, {%0,%1,%2,%3};"
        : "+f"(c[0]), "+f"(c[1]), "+f"(c[2]), "+f"(c[3])
        : "r"(a[0]), "r"(a[1]), "r"(a[2]), "r"(a[3]), "r"(b[0]), "r"(b[1]));
}

// ---------------------------------------------------------------------------
// K0: zero the GAP accumulator
// ---------------------------------------------------------------------------
__global__ void k_zero()
{
    g_gap[threadIdx.x] = 0.0f;
}

// ---------------------------------------------------------------------------
// K1: bilinear x2 upsample (align_corners) -> fp16 planes + fused GAP.
// Block = (oy, g, b); thread = ox. Input rows y0,y0+1 of 8 channels staged
// in smem (uniform y0 per block), then per-thread 4-point interp.
// ---------------------------------------------------------------------------
__global__ void __launch_bounds__(256) k_upsample(const float* __restrict__ x)
{
    __shared__ float sX[8][2][WIN];
    __shared__ float swarp[8][8];

    int oy = blockIdx.x;
    int g  = blockIdx.y;
    int b  = blockIdx.z;
    int ox = threadIdx.x;
    int lane = ox & 31;
    int wrp  = ox >> 5;

    float py = (float)oy * RATIO;
    int   y0 = min((int)py, HIN - 2);
    float wy = py - (float)y0;

    // stage input rows y0, y0+1 for 8 channels
    const float* base = x + ((size_t)b * CIN + g * 8) * (HIN * WIN);
    for (int i = threadIdx.x; i < 8 * 2 * WIN; i += 256) {
        int k = i >> 8;
        int r = (i >> 7) & 1;
        int c = i & 127;
        sX[k][r][c] = __ldg(base + (size_t)k * (HIN * WIN) + (y0 + r) * WIN + c);
    }
    __syncthreads();

    float px = (float)ox * RATIO;
    int   x0 = min((int)px, WIN - 2);
    float wx = px - (float)x0;

    float v[8];
    ushort4 hout[2];
    u32 hw[4];
    #pragma unroll
    for (int k = 0; k < 8; k++) {
        float a  = sX[k][0][x0];
        float bb = sX[k][0][x0 + 1];
        float cv = sX[k][1][x0];
        float d  = sX[k][1][x0 + 1];
        float v0 = a  * (1.0f - wy) + cv * wy;   // rows first
        float v1 = bb * (1.0f - wy) + d  * wy;
        v[k] = v0 * (1.0f - wx) + v1 * wx;       // then cols
    }
    #pragma unroll
    for (int j = 0; j < 4; j++) {
        u32 p = (u32)__half_as_ushort(__float2half(v[2 * j]));
        p |= (u32)__half_as_ushort(__float2half(v[2 * j + 1])) << 16;
        hw[j] = p;
    }
    ((uint4*)g_xh)[((size_t)(b * 8 + g) * HO + oy) * WO + ox] =
        make_uint4(hw[0], hw[1], hw[2], hw[3]);

    // fused GAP: per-channel block reduction -> atomic
    #pragma unroll
    for (int k = 0; k < 8; k++) {
        float s = v[k];
        #pragma unroll
        for (int off = 16; off > 0; off >>= 1)
            s += __shfl_xor_sync(0xFFFFFFFFu, s, off);
        if (lane == 0) swarp[wrp][k] = s;
    }
    __syncthreads();
    if (threadIdx.x < 8) {
        float s = 0.0f;
        #pragma unroll
        for (int wq = 0; wq < 8; wq++) s += swarp[wq][threadIdx.x];
        atomicAdd(&g_gap[b * CIN + g * 8 + threadIdx.x],
                  s * (1.0f / (float)(HO * WO)));
    }
}

// ---------------------------------------------------------------------------
// K2: attention MLP + weight fold -> fp16 weights [b][q][co][ci]
// ---------------------------------------------------------------------------
__global__ void k_attention(
    const float* __restrict__ fc_w,
    const float* __restrict__ bna_g, const float* __restrict__ bna_b,
    const float* __restrict__ bna_m, const float* __restrict__ bna_v,
    const float* __restrict__ ch_w,  const float* __restrict__ ch_b,
    const float* __restrict__ fil_w, const float* __restrict__ fil_b,
    const float* __restrict__ sp_w,  const float* __restrict__ sp_b,
    const float* __restrict__ k_w,   const float* __restrict__ k_b,
    const float* __restrict__ weight,
    const float* __restrict__ bn_g,  const float* __restrict__ bn_b,
    const float* __restrict__ bn_m,  const float* __restrict__ bn_v)
{
    int b = blockIdx.x;
    int t = threadIdx.x;
    __shared__ float sh[ATT];
    __shared__ float sch[CIN];
    __shared__ float sfs[COUT];
    __shared__ float ssp[9];
    __shared__ float sraw[KNUM];
    __shared__ float skk[KNUM];

    if (t < ATT) {
        const float* g = g_gap + b * CIN;
        float acc = 0.0f;
        #pragma unroll
        for (int ci = 0; ci < CIN; ci++) acc += fc_w[t * CIN + ci] * g[ci];
        acc = (acc - bna_m[t]) * rsqrtf(bna_v[t] + EPS) * bna_g[t] + bna_b[t];
        sh[t] = fmaxf(acc, 0.0f);
    }
    __syncthreads();
    if (t < CIN) {
        float a = ch_b[t];
        #pragma unroll
        for (int j = 0; j < ATT; j++) a += ch_w[t * ATT + j] * sh[j];
        sch[t] = 1.0f / (1.0f + expf(-a));
    } else if (t < CIN + COUT) {
        int co = t - CIN;
        float a = fil_b[co];
        #pragma unroll
        for (int j = 0; j < ATT; j++) a += fil_w[co * ATT + j] * sh[j];
        float fil = 1.0f / (1.0f + expf(-a));
        sfs[co] = fil * bn_g[co] * rsqrtf(bn_v[co] + EPS);
    } else if (t < CIN + COUT + 9) {
        int q = t - CIN - COUT;
        float a = sp_b[q];
        #pragma unroll
        for (int j = 0; j < ATT; j++) a += sp_w[q * ATT + j] * sh[j];
        ssp[q] = 1.0f / (1.0f + expf(-a));
    } else if (t < CIN + COUT + 9 + KNUM) {
        int k = t - CIN - COUT - 9;
        float a = k_b[k];
        #pragma unroll
        for (int j = 0; j < ATT; j++) a += k_w[k * ATT + j] * sh[j];
        sraw[k] = a;
    }
    __syncthreads();
    if (t == 0) {
        float m  = fmaxf(sraw[0], sraw[1]);
        float e0 = expf(sraw[0] - m);
        float e1 = expf(sraw[1] - m);
        float inv = 1.0f / (e0 + e1);
        skk[0] = e0 * inv;
        skk[1] = e1 * inv;
    }
    __syncthreads();

    const int WSZ = COUT * CIN * 9;
    for (int idx = t; idx < WSZ; idx += blockDim.x) {
        int co  = idx / (CIN * 9);
        int rem = idx % (CIN * 9);
        int ci  = rem / 9;
        int q   = rem % 9;
        float w = skk[0] * weight[idx] + skk[1] * weight[WSZ + idx];
        w = w * ssp[q] * sch[ci] * sfs[co];
        g_w[(((size_t)b * 9 + q) * COUT + co) * CIN + ci] = __float2half(w);
    }
    if (b == 0 && t < COUT)
        g_bias[t] = bn_b[t] - bn_m[t] * bn_g[t] * rsqrtf(bn_v[t] + EPS);
}

// ---------------------------------------------------------------------------
// K3: implicit-GEMM conv on HMMA (mma.sync m16n8k16 fp16, single pass).
// CTA tile: (b, 2 output rows x 64 cols). 8 warps; warp = 16 px x 32 cout.
// A smem: 4 rows x 66 px x 64 cin fp16, filled by coalesced uint4 copies
// from the materialized g_xh. B smem: 9 tap matrices 32x64 fp16.
// 70.7 KB smem -> 2-3 CTAs/SM.
// ---------------------------------------------------------------------------
#define AROWB 8448            // 66 * 128 bytes
#define OFF_B 0               // 9 * 4096 = 36864
#define OFF_A 36864
#define SMEM_TOTAL (OFF_A + 4 * AROWB)   // 70656

#define SWZC(byte, r) ((byte) ^ (((r) & 7) << 4))

__global__ void __launch_bounds__(256, 2)
k_conv(float* __restrict__ out)
{
    extern __shared__ char smem[];
    u32 sb = smem_to_u32(smem);
    int tid  = threadIdx.x;
    int w    = tid >> 5;
    int lane = tid & 31;
    int b    = blockIdx.z;
    int r0   = blockIdx.y * 2;
    int c0   = blockIdx.x * 64;

    // ---- fill B: 9 q x 32 n x 8 chunks ------------------------------------
    for (int i = tid; i < 2304; i += 256) {
        int q    = i / 256;
        int rem2 = i % 256;
        int n    = rem2 >> 3;
        int g    = rem2 & 7;
        uint4 v = *(const uint4*)(g_w +
            (((size_t)b * 9 + q) * COUT + n) * CIN + g * 8);
        *(uint4*)(smem + OFF_B + q * 4096 + n * 128 + SWZC(g * 16, n)) = v;
    }

    // ---- fill A from g_xh: 4 rows x 8 chunks x 66 px (p fastest) ----------
    const uint4* xh4 = (const uint4*)g_xh;
    for (int i = tid; i < 4 * 8 * 66; i += 256) {
        int row = i / (8 * 66);
        int rem = i % (8 * 66);
        int g   = rem / 66;
        int p   = rem % 66;
        int oy  = r0 - 1 + row;
        int oc  = c0 - 1 + p;
        uint4 v = make_uint4(0, 0, 0, 0);
        if ((unsigned)oy < (unsigned)HO && (unsigned)oc < (unsigned)WO)
            v = xh4[((size_t)(b * 8 + g) * HO + oy) * WO + oc];
        *(uint4*)(smem + OFF_A + row * AROWB + p * 128 + SWZC(g * 16, p)) = v;
    }
    __syncthreads();

    // ---- mainloop: 9 taps x 4 k-steps -------------------------------------
    float acc[4][4];
    #pragma unroll
    for (int nt = 0; nt < 4; nt++)
        #pragma unroll
        for (int r = 0; r < 4; r++) acc[nt][r] = 0.0f;

    int wrow = w >> 2;             // output row within tile (0..1)
    int wcol = (w & 3) * 16;       // col base within 64-tile

    #pragma unroll 1
    for (int q = 0; q < 9; q++) {
        int ky = q / 3, kx = q % 3;
        u32 arow  = sb + OFF_A + (wrow + ky) * AROWB;
        u32 bbase = sb + OFF_B + q * 4096;
        #pragma unroll
        for (int ks = 0; ks < 4; ks++) {
            int kb = ks * 32;                 // 16 fp16 = 32 bytes
            u32 afr[4];
            {
                int p = wcol + (lane & 15) + kx;
                u32 addr = arow + p * 128 +
                           SWZC(kb + ((lane >> 4) ? 16 : 0), p);
                ldsm_x4(afr, addr);
            }
            #pragma unroll
            for (int nt = 0; nt < 4; nt++) {
                int n = nt * 8 + (lane & 7);
                u32 addr = bbase + n * 128 +
                           SWZC(kb + ((lane >> 3) & 1) * 16, n);
                u32 bfr[2];
                ldsm_x2(bfr, addr);
                mma_fp16(acc[nt], afr, bfr);
            }
        }
    }

    // ---- epilogue: bias + exact-erf GELU ----------------------------------
    int row  = r0 + wrow;
    int colb = c0 + wcol + (lane >> 2);
    #pragma unroll
    for (int nt = 0; nt < 4; nt++) {
        int co0 = nt * 8 + (lane & 3) * 2;
        float b0 = g_bias[co0];
        float b1 = g_bias[co0 + 1];
        #pragma unroll
        for (int r = 0; r < 4; r++) {
            int co = co0 + (r & 1);
            int cc = colb + ((r >> 1) ? 8 : 0);
            float v = acc[nt][r] + ((r & 1) ? b1 : b0);
            out[(((size_t)b * COUT + co) * HO + row) * WO + cc] =
                0.5f * v * (1.0f + erff(v * 0.70710678118654752f));
        }
    }
}

// ---------------------------------------------------------------------------
extern "C" void kernel_launch(void* const* d_in, const int* in_sizes, int n_in,
                              void* d_out, int out_size)
{
    const float* x      = (const float*)d_in[0];
    const float* fc_w   = (const float*)d_in[1];
    const float* bna_g  = (const float*)d_in[2];
    const float* bna_b  = (const float*)d_in[3];
    const float* bna_m  = (const float*)d_in[4];
    const float* bna_v  = (const float*)d_in[5];
    const float* ch_w   = (const float*)d_in[6];
    const float* ch_b   = (const float*)d_in[7];
    const float* fil_w  = (const float*)d_in[8];
    const float* fil_b  = (const float*)d_in[9];
    const float* sp_w   = (const float*)d_in[10];
    const float* sp_b   = (const float*)d_in[11];
    const float* k_w    = (const float*)d_in[12];
    const float* k_b    = (const float*)d_in[13];
    const float* weight = (const float*)d_in[14];
    const float* bn_g   = (const float*)d_in[15];
    const float* bn_b   = (const float*)d_in[16];
    const float* bn_m   = (const float*)d_in[17];
    const float* bn_v   = (const float*)d_in[18];

    cudaFuncSetAttribute(k_conv, cudaFuncAttributeMaxDynamicSharedMemorySize,
                         SMEM_TOTAL);

    k_zero<<<1, B_ * CIN>>>();
    k_upsample<<<dim3(HO, 8, B_), 256>>>(x);
    k_attention<<<B_, 256>>>(fc_w, bna_g, bna_b, bna_m, bna_v,
                             ch_w, ch_b, fil_w, fil_b, sp_w, sp_b, k_w, k_b,
                             weight, bn_g, bn_b, bn_m, bn_v);
    k_conv<<<dim3(WO / 64, HO / 2, B_), 256, SMEM_TOTAL>>>((float*)d_out);
}